// round 14
// baseline (speedup 1.0000x reference)
#include <cuda_runtime.h>
#include <cuda_fp16.h>
#include <cstdint>

// ---------------------------------------------------------------------------
// out = relu(x·W1effᵀ + b1)·fc2ᵀ + b2   via mma.sync m16n8k16 (fp16 in, fp32 acc)
// B (104x784 fp16, 163KB) resident in smem (staged once per CTA).
// A: LDG.128 FULL 128-byte lines (4 rows/LDG, 2 k-steps) -> cvt fp16 ->
// warp-private smem tile (stride 80 = conflict-free ldmatrix) -> ldsm x4.
// No shuffles, no CTA barriers in mainloop (only __syncwarp per 2 steps).
// B fragments double-buffered across k-steps, LDSMs interleaved with MMAs.
// 448 thr = 14 warps, persistent grid=148, 2 chunks/warp.
// ---------------------------------------------------------------------------

#define KW      784
#define NSTEP   49                 // 784 / 16
#define BSTRIDE 3328               // 104 n-rows * 32 B per k-step
#define BSMEM   (NSTEP * BSTRIDE)  // 163072 B
#define AROW    80                 // A smem row stride (bank-tiling magic)
#define ABUF    (16 * AROW)        // 1280 B per buffer
#define AWARP   (2 * ABUF)         // 2560 B per warp (double buffer)
#define NWARPS  14
#define DYNSM   (BSMEM + NWARPS * AWARP)   // 198912 B
#define CTA_T   448
#define ROWS_W  16

__device__ __half g_w1[104 * KW];

// ---------------- weight fold + fp16 conversion ----------------------------

__global__ void build_w1(const float* __restrict__ conv_w,
                         const float* __restrict__ fc1_w) {
    int idx = blockIdx.x * blockDim.x + threadIdx.x;
    if (idx >= 104 * KW) return;
    int n = idx / KW;
    int k = idx % KW;
    float v = 0.f;
    if (n < 100) {
        int y  = k / 28;
        int xx = k % 28;
        #pragma unroll
        for (int i = 0; i < 3; i++) {
            int r = y - i;
            if (r < 0 || r > 25) continue;
            #pragma unroll
            for (int j = 0; j < 3; j++) {
                int c = xx - j;
                if (c < 0 || c > 25) continue;
                v += fc1_w[n * 676 + r * 26 + c] * conv_w[i * 3 + j];
            }
        }
    }
    g_w1[n * KW + k] = __float2half(v);
}

// ---------------- PTX helpers ----------------------------------------------

__device__ __forceinline__ uint32_t smem_u32(const void* p) {
    uint32_t a;
    asm("{ .reg .u64 t; cvta.to.shared.u64 t, %1; cvt.u32.u64 %0, t; }"
        : "=r"(a) : "l"(p));
    return a;
}

__device__ __forceinline__ void ldsm_x4(uint32_t& r0, uint32_t& r1,
                                        uint32_t& r2, uint32_t& r3, uint32_t addr) {
    asm volatile("ldmatrix.sync.aligned.m8n8.x4.shared.b16 {%0,%1,%2,%3}, [%4];"
        : "=r"(r0), "=r"(r1), "=r"(r2), "=r"(r3) : "r"(addr));
}

__device__ __forceinline__ void ldsm_x2(uint32_t& r0, uint32_t& r1, uint32_t addr) {
    asm volatile("ldmatrix.sync.aligned.m8n8.x2.shared.b16 {%0,%1}, [%2];"
        : "=r"(r0), "=r"(r1) : "r"(addr));
}

__device__ __forceinline__ void mma_f16(float* c,
                                        uint32_t a0, uint32_t a1, uint32_t a2, uint32_t a3,
                                        uint32_t b0, uint32_t b1) {
    asm volatile(
        "mma.sync.aligned.m16n8k16.row.col.f32.f16.f16.f32 "
        "{%0,%1,%2,%3}, {%4,%5,%6,%7}, {%8,%9}, {%0,%1,%2,%3};"
        : "+f"(c[0]), "+f"(c[1]), "+f"(c[2]), "+f"(c[3])
        : "r"(a0), "r"(a1), "r"(a2), "r"(a3), "r"(b0), "r"(b1));
}

__device__ __forceinline__ void sts64(uint32_t addr, uint32_t v0, uint32_t v1) {
    asm volatile("st.shared.v2.b32 [%0], {%1,%2};" :: "r"(addr), "r"(v0), "r"(v1)
        : "memory");
}

// ---------------- fused GEMM + epilogue ------------------------------------

__global__ __launch_bounds__(CTA_T, 1)
void fused_gemm(const float* __restrict__ x,
                const float* __restrict__ fc1_b,
                const float* __restrict__ fc2_w,
                const float* __restrict__ fc2_b,
                float* __restrict__ out, int Brows) {
    extern __shared__ __align__(128) uint8_t dynsmem[];   // B + A tiles
    __shared__ float b1s[128];
    __shared__ float w2s[100][12];
    __shared__ float b2v[16];

    const int tid = threadIdx.x;
    const int wid = tid >> 5;            // 0..13
    const int lid = tid & 31;
    const int qid = lid & 3;
    const int qrow = lid >> 2;           // 0..7

    const uint32_t bbase = smem_u32(dynsmem);
    const uint32_t abase = bbase + BSMEM + (uint32_t)wid * AWARP;

    // ---- stage B once: g_w1[n][k] -> [step s][n][2x16B], swizzled
    for (int idx = tid; idx < NSTEP * 104 * 2; idx += CTA_T) {
        int cch = idx & 1;
        int n = (idx >> 1) % 104;
        int s = (idx >> 1) / 104;
        uint32_t dst = bbase + (uint32_t)(s * 104 + n) * 32
                     + ((cch ^ ((n >> 2) & 1)) << 4);
        const __half* src = &g_w1[n * KW + s * 16 + cch * 8];
        asm volatile("cp.async.cg.shared.global [%0], [%1], 16;"
                     :: "r"(dst), "l"(src) : "memory");
    }
    asm volatile("cp.async.commit_group;" ::: "memory");

    if (tid < 128) b1s[tid] = (tid < 100) ? fc1_b[tid] : 0.f;
    if (tid < 100) {
        #pragma unroll
        for (int j = 0; j < 10; j++) w2s[tid][j] = fc2_w[j * 100 + tid];
    }
    if (tid < 10) b2v[tid] = fc2_b[tid];

    // ---- B ldmatrix lane offsets
    const int b_nl = ((lid >> 4) & 1) * 8 + (lid & 7);
    const int b_ko = (lid >> 3) & 1;
    uint32_t boff[6];
    #pragma unroll
    for (int tp = 0; tp < 6; tp++) {
        int n_l = tp * 16 + b_nl;
        boff[tp] = (uint32_t)(n_l * 32 + ((b_ko ^ ((n_l >> 2) & 1)) << 4));
    }
    const int nx = 96 + (lid & 7);
    const uint32_t bxoff = (uint32_t)(nx * 32 + ((b_ko ^ ((nx >> 2) & 1)) << 4));

    // ---- A lane geometry
    // LDG i covers rows 4i..4i+3: lane -> row 4i+(lid>>3), float col (lid&7)*4
    const int rb    = lid >> 3;                       // 0..3 row-in-ldg
    const int fcol  = (lid & 7) * 4;                  // float col in 32-float blk
    // A smem: row-major stride 80 (linear, conflict-free by bank tiling)
    const uint32_t a_st = (uint32_t)(rb * AROW + (lid & 7) * 8);
    const uint32_t a_ld = (uint32_t)((lid & 15) * AROW + ((lid >> 4) << 4));
    const bool lane_lo  = (lid & 7) < 4;              // tail-block valid lanes

    asm volatile("cp.async.wait_group 0;" ::: "memory");
    __syncthreads();
    // no CTA barriers below — warps fully independent

    const int nck   = (Brows + ROWS_W - 1) / ROWS_W;       // 4096
    const int nwarp = gridDim.x * NWARPS;                  // 2072
    const int gw    = blockIdx.x * NWARPS + wid;

    for (int ck = gw; ck < nck; ck += nwarp) {
        const int mbase = ck * ROWS_W;
        const float* xb = x + (size_t)(mbase + rb) * KW + fcol;

        bool vr[4], v24[4];
        #pragma unroll
        for (int i = 0; i < 4; i++) {
            int r = mbase + 4 * i + rb;
            vr[i]  = r < Brows;
            v24[i] = vr[i] && (lane_lo || (r + 1 < Brows));
        }

        float c[13][4];
        #pragma unroll
        for (int t = 0; t < 13; t++)
            #pragma unroll
            for (int q = 0; q < 4; q++) c[t][q] = 0.f;

        float4 f4[4];
        uint32_t bfA[26], bfB[26];

        // LOAD_BLK: 4 LDG.128, full 128B lines (2 k-steps), predicated
        #define LOAD_BLK(blk, P) do {                                         \
            const float4 z4 = make_float4(0.f, 0.f, 0.f, 0.f);                \
            f4[0] = (P)[0] ? *reinterpret_cast<const float4*>(xb + (blk) * 32)            : z4; \
            f4[1] = (P)[1] ? *reinterpret_cast<const float4*>(xb + 4 * KW + (blk) * 32)   : z4; \
            f4[2] = (P)[2] ? *reinterpret_cast<const float4*>(xb + 8 * KW + (blk) * 32)   : z4; \
            f4[3] = (P)[3] ? *reinterpret_cast<const float4*>(xb + 12 * KW + (blk) * 32)  : z4; \
        } while (0)

        // CVTSTS: fp32->fp16 and store 8B per thread per ldg-group
        #define CVTSTS(bufsel) do {                                           \
            uint32_t ab = abase + (bufsel) * ABUF + a_st;                     \
            _Pragma("unroll")                                                 \
            for (int i = 0; i < 4; i++) {                                     \
                __half2 h01 = __floats2half2_rn(f4[i].x, f4[i].y);            \
                __half2 h23 = __floats2half2_rn(f4[i].z, f4[i].w);            \
                sts64(ab + i * (4 * AROW),                                    \
                      *reinterpret_cast<uint32_t*>(&h01),                     \
                      *reinterpret_cast<uint32_t*>(&h23));                    \
            }                                                                 \
        } while (0)

        #define LDSM_STEP(BF, s) do {                                         \
            const uint32_t sb_ = bbase + (uint32_t)(s) * BSTRIDE;             \
            ldsm_x4((BF)[0],  (BF)[1],  (BF)[2],  (BF)[3],  sb_ + boff[0]);   \
            ldsm_x4((BF)[4],  (BF)[5],  (BF)[6],  (BF)[7],  sb_ + boff[1]);   \
            ldsm_x4((BF)[8],  (BF)[9],  (BF)[10], (BF)[11], sb_ + boff[2]);   \
            ldsm_x4((BF)[12], (BF)[13], (BF)[14], (BF)[15], sb_ + boff[3]);   \
            ldsm_x4((BF)[16], (BF)[17], (BF)[18], (BF)[19], sb_ + boff[4]);   \
            ldsm_x4((BF)[20], (BF)[21], (BF)[22], (BF)[23], sb_ + boff[5]);   \
            ldsm_x2((BF)[24], (BF)[25], sb_ + bxoff);                         \
        } while (0)

        // MMA phase using frags CUR, prefetching step (s+1) frags into NXT
        #define STEP_PIPE(s, CUR, NXT, a0, a1, a2, a3) do {                   \
            const uint32_t sbn = bbase + (uint32_t)((s) + 1) * BSTRIDE;       \
            ldsm_x4((NXT)[0], (NXT)[1], (NXT)[2], (NXT)[3], sbn + boff[0]);   \
            mma_f16(c[0],  a0, a1, a2, a3, (CUR)[0],  (CUR)[1]);              \
            mma_f16(c[1],  a0, a1, a2, a3, (CUR)[2],  (CUR)[3]);              \
            ldsm_x4((NXT)[4], (NXT)[5], (NXT)[6], (NXT)[7], sbn + boff[1]);   \
            mma_f16(c[2],  a0, a1, a2, a3, (CUR)[4],  (CUR)[5]);              \
            mma_f16(c[3],  a0, a1, a2, a3, (CUR)[6],  (CUR)[7]);              \
            ldsm_x4((NXT)[8], (NXT)[9], (NXT)[10], (NXT)[11], sbn + boff[2]); \
            mma_f16(c[4],  a0, a1, a2, a3, (CUR)[8],  (CUR)[9]);              \
            mma_f16(c[5],  a0, a1, a2, a3, (CUR)[10], (CUR)[11]);             \
            ldsm_x4((NXT)[12], (NXT)[13], (NXT)[14], (NXT)[15], sbn + boff[3]); \
            mma_f16(c[6],  a0, a1, a2, a3, (CUR)[12], (CUR)[13]);             \
            mma_f16(c[7],  a0, a1, a2, a3, (CUR)[14], (CUR)[15]);             \
            ldsm_x4((NXT)[16], (NXT)[17], (NXT)[18], (NXT)[19], sbn + boff[4]); \
            mma_f16(c[8],  a0, a1, a2, a3, (CUR)[16], (CUR)[17]);             \
            mma_f16(c[9],  a0, a1, a2, a3, (CUR)[18], (CUR)[19]);             \
            ldsm_x4((NXT)[20], (NXT)[21], (NXT)[22], (NXT)[23], sbn + boff[5]); \
            mma_f16(c[10], a0, a1, a2, a3, (CUR)[20], (CUR)[21]);             \
            mma_f16(c[11], a0, a1, a2, a3, (CUR)[22], (CUR)[23]);             \
            ldsm_x2((NXT)[24], (NXT)[25], sbn + bxoff);                       \
            mma_f16(c[12], a0, a1, a2, a3, (CUR)[24], (CUR)[25]);             \
        } while (0)

        #define STEP_LAST(CUR, a0, a1, a2, a3) do {                           \
            mma_f16(c[0],  a0, a1, a2, a3, (CUR)[0],  (CUR)[1]);              \
            mma_f16(c[1],  a0, a1, a2, a3, (CUR)[2],  (CUR)[3]);              \
            mma_f16(c[2],  a0, a1, a2, a3, (CUR)[4],  (CUR)[5]);              \
            mma_f16(c[3],  a0, a1, a2, a3, (CUR)[6],  (CUR)[7]);              \
            mma_f16(c[4],  a0, a1, a2, a3, (CUR)[8],  (CUR)[9]);              \
            mma_f16(c[5],  a0, a1, a2, a3, (CUR)[10], (CUR)[11]);             \
            mma_f16(c[6],  a0, a1, a2, a3, (CUR)[12], (CUR)[13]);             \
            mma_f16(c[7],  a0, a1, a2, a3, (CUR)[14], (CUR)[15]);             \
            mma_f16(c[8],  a0, a1, a2, a3, (CUR)[16], (CUR)[17]);             \
            mma_f16(c[9],  a0, a1, a2, a3, (CUR)[18], (CUR)[19]);             \
            mma_f16(c[10], a0, a1, a2, a3, (CUR)[20], (CUR)[21]);             \
            mma_f16(c[11], a0, a1, a2, a3, (CUR)[22], (CUR)[23]);             \
            mma_f16(c[12], a0, a1, a2, a3, (CUR)[24], (CUR)[25]);             \
        } while (0)

        // ---- prologue: block 0 -> buf0; B frags for step 0
        LOAD_BLK(0, vr);
        CVTSTS(0);
        LDSM_STEP(bfA, 0);
        __syncwarp();

        // ---- main: blocks j=0..23 cover steps 0..47; block j+1 prefetched
        #pragma unroll 1
        for (int j = 0; j < 24; j++) {
            const int buf = j & 1;
            if (j + 1 < 24) LOAD_BLK(j + 1, vr);
            else            LOAD_BLK(24, v24);        // tail block: masked lanes

            uint32_t a0, a1, a2, a3;
            ldsm_x4(a0, a1, a2, a3, abase + buf * ABUF + a_ld);        // step 2j
            STEP_PIPE(2 * j, bfA, bfB, a0, a1, a2, a3);

            ldsm_x4(a0, a1, a2, a3, abase + buf * ABUF + a_ld + 32);   // step 2j+1
            CVTSTS(buf ^ 1);
            STEP_PIPE(2 * j + 1, bfB, bfA, a0, a1, a2, a3);
            __syncwarp();
        }

        // ---- tail: step 48 (block 24 sits in buf0; frags in bfA)
        {
            uint32_t a0, a1, a2, a3;
            ldsm_x4(a0, a1, a2, a3, abase + 0 * ABUF + a_ld);
            STEP_LAST(bfA, a0, a1, a2, a3);
        }

        #undef LOAD_BLK
        #undef CVTSTS
        #undef LDSM_STEP
        #undef STEP_PIPE
        #undef STEP_LAST

        // ---- epilogue: h = relu(c + b1); p = h·fc2ᵀ; quad-reduce; + b2
        float p0[10], p1[10];
        #pragma unroll
        for (int j = 0; j < 10; j++) { p0[j] = 0.f; p1[j] = 0.f; }

        #pragma unroll
        for (int t = 0; t < 13; t++) {
            #pragma unroll
            for (int e = 0; e < 2; e++) {
                int n = t * 8 + qid * 2 + e;
                if (n < 100) {
                    float h0 = fmaxf(c[t][0 + e] + b1s[n], 0.f);  // row qrow
                    float h1 = fmaxf(c[t][2 + e] + b1s[n], 0.f);  // row qrow+8
                    #pragma unroll
                    for (int j = 0; j < 10; j++) {
                        p0[j] = fmaf(h0, w2s[n][j], p0[j]);
                        p1[j] = fmaf(h1, w2s[n][j], p1[j]);
                    }
                }
            }
        }
        #pragma unroll
        for (int mask = 2; mask >= 1; mask >>= 1) {
            #pragma unroll
            for (int j = 0; j < 10; j++) {
                p0[j] += __shfl_xor_sync(0xffffffffu, p0[j], mask);
                p1[j] += __shfl_xor_sync(0xffffffffu, p1[j], mask);
            }
        }
        if (qid == 0) {
            int r0 = mbase + qrow;
            int r1 = r0 + 8;
            if (r0 < Brows) {
                #pragma unroll
                for (int j = 0; j < 10; j++)
                    out[(size_t)r0 * 10 + j] = p0[j] + b2v[j];
            }
            if (r1 < Brows) {
                #pragma unroll
                for (int j = 0; j < 10; j++)
                    out[(size_t)r1 * 10 + j] = p1[j] + b2v[j];
            }
        }
    }
}

// ---------------- launch ---------------------------------------------------

extern "C" void kernel_launch(void* const* d_in, const int* in_sizes, int n_in,
                              void* d_out, int out_size) {
    const float* x      = (const float*)d_in[0];
    const float* conv_w = (const float*)d_in[1];
    const float* fc1_w  = (const float*)d_in[2];
    const float* fc1_b  = (const float*)d_in[3];
    const float* fc2_w  = (const float*)d_in[4];
    const float* fc2_b  = (const float*)d_in[5];
    float* out = (float*)d_out;

    int Brows = in_sizes[0] / KW;

    build_w1<<<(104 * KW + 255) / 256, 256>>>(conv_w, fc1_w);

    cudaFuncSetAttribute(fused_gemm, cudaFuncAttributeMaxDynamicSharedMemorySize,
                         DYNSM);

    fused_gemm<<<148, CTA_T, DYNSM>>>(x, fc1_b, fc2_w, fc2_b, out, Brows);
}

// round 15
// speedup vs baseline: 1.2651x; 1.2651x over previous
#include <cuda_runtime.h>
#include <cuda_fp16.h>
#include <cstdint>

// ---------------------------------------------------------------------------
// out = relu(x·W1effᵀ + b1)·fc2ᵀ + b2   via mma.sync m16n8k16 (fp16 in, fp32 acc)
// R12 structure (proven 63.2us): B resident in smem, A via LDG.64-pairs +
// shuffle rebuild, B fragments double-buffered across k-steps with LDSMs
// interleaved between MMAs. THIS ROUND: 512 thr = 16 warps (regs 124 <= 128
// cap) + exact spread assignment of the 1728 second-round chunks across all
// SMs (no idle-SM round 2).
// ---------------------------------------------------------------------------

#define KW      784
#define NSTEP   49                 // 784 / 16
#define BSTRIDE 3328               // 104 n-rows * 32 B per k-step
#define BSMEM   (NSTEP * BSTRIDE)  // 163072 B
#define CTA_T   512
#define ROWS_W  16

__device__ __half g_w1[104 * KW];

// ---------------- weight fold + fp16 conversion ----------------------------

__global__ void build_w1(const float* __restrict__ conv_w,
                         const float* __restrict__ fc1_w) {
    int idx = blockIdx.x * blockDim.x + threadIdx.x;
    if (idx >= 104 * KW) return;
    int n = idx / KW;
    int k = idx % KW;
    float v = 0.f;
    if (n < 100) {
        int y  = k / 28;
        int xx = k % 28;
        #pragma unroll
        for (int i = 0; i < 3; i++) {
            int r = y - i;
            if (r < 0 || r > 25) continue;
            #pragma unroll
            for (int j = 0; j < 3; j++) {
                int c = xx - j;
                if (c < 0 || c > 25) continue;
                v += fc1_w[n * 676 + r * 26 + c] * conv_w[i * 3 + j];
            }
        }
    }
    g_w1[n * KW + k] = __float2half(v);
}

// ---------------- PTX helpers ----------------------------------------------

__device__ __forceinline__ uint32_t smem_u32(const void* p) {
    uint32_t a;
    asm("{ .reg .u64 t; cvta.to.shared.u64 t, %1; cvt.u32.u64 %0, t; }"
        : "=r"(a) : "l"(p));
    return a;
}

__device__ __forceinline__ void ldsm_x4(uint32_t& r0, uint32_t& r1,
                                        uint32_t& r2, uint32_t& r3, uint32_t addr) {
    asm volatile("ldmatrix.sync.aligned.m8n8.x4.shared.b16 {%0,%1,%2,%3}, [%4];"
        : "=r"(r0), "=r"(r1), "=r"(r2), "=r"(r3) : "r"(addr));
}

__device__ __forceinline__ void ldsm_x2(uint32_t& r0, uint32_t& r1, uint32_t addr) {
    asm volatile("ldmatrix.sync.aligned.m8n8.x2.shared.b16 {%0,%1}, [%2];"
        : "=r"(r0), "=r"(r1) : "r"(addr));
}

__device__ __forceinline__ void mma_f16(float* c,
                                        uint32_t a0, uint32_t a1, uint32_t a2, uint32_t a3,
                                        uint32_t b0, uint32_t b1) {
    asm volatile(
        "mma.sync.aligned.m16n8k16.row.col.f32.f16.f16.f32 "
        "{%0,%1,%2,%3}, {%4,%5,%6,%7}, {%8,%9}, {%0,%1,%2,%3};"
        : "+f"(c[0]), "+f"(c[1]), "+f"(c[2]), "+f"(c[3])
        : "r"(a0), "r"(a1), "r"(a2), "r"(a3), "r"(b0), "r"(b1));
}

// ---------------- fused GEMM + epilogue ------------------------------------

__global__ __launch_bounds__(CTA_T, 1)
void fused_gemm(const float* __restrict__ x,
                const float* __restrict__ fc1_b,
                const float* __restrict__ fc2_w,
                const float* __restrict__ fc2_b,
                float* __restrict__ out, int Brows) {
    extern __shared__ __align__(128) uint8_t dynsmem[];   // B: 163072 B
    __shared__ float b1s[128];
    __shared__ float w2s[100][12];
    __shared__ float b2v[16];

    const int tid = threadIdx.x;
    const int wid = tid >> 5;            // 0..15
    const int lid = tid & 31;
    const int qid = lid & 3;
    const int qrow = lid >> 2;           // 0..7

    const uint32_t bbase = smem_u32(dynsmem);

    // ---- stage B once: g_w1[n][k] -> [step s][n][2x16B], swizzled
    for (int idx = tid; idx < NSTEP * 104 * 2; idx += CTA_T) {
        int cch = idx & 1;
        int n = (idx >> 1) % 104;
        int s = (idx >> 1) / 104;
        uint32_t dst = bbase + (uint32_t)(s * 104 + n) * 32
                     + ((cch ^ ((n >> 2) & 1)) << 4);
        const __half* src = &g_w1[n * KW + s * 16 + cch * 8];
        asm volatile("cp.async.cg.shared.global [%0], [%1], 16;"
                     :: "r"(dst), "l"(src) : "memory");
    }
    asm volatile("cp.async.commit_group;" ::: "memory");

    if (tid < 128) b1s[tid] = (tid < 100) ? fc1_b[tid] : 0.f;
    if (tid < 100) {
        #pragma unroll
        for (int j = 0; j < 10; j++) w2s[tid][j] = fc2_w[j * 100 + tid];
    }
    if (tid < 10) b2v[tid] = fc2_b[tid];

    // ---- B ldmatrix lane offsets (constant per thread)
    const int b_nl = ((lid >> 4) & 1) * 8 + (lid & 7);
    const int b_ko = (lid >> 3) & 1;
    uint32_t boff[6];
    #pragma unroll
    for (int tp = 0; tp < 6; tp++) {
        int n_l = tp * 16 + b_nl;
        boff[tp] = (uint32_t)(n_l * 32 + ((b_ko ^ ((n_l >> 2) & 1)) << 4));
    }
    const int nx = 96 + (lid & 7);
    const uint32_t bxoff = (uint32_t)(nx * 32 + ((b_ko ^ ((nx >> 2) & 1)) << 4));

    // shuffle sources for A fragment rebuild (proven R9-R12)
    const int src0 = (lid & 28) | (qid >> 1);
    const int src1 = src0 + 2;
    const bool hi_half = (qid & 1);

    asm volatile("cp.async.wait_group 0;" ::: "memory");
    __syncthreads();
    // no barriers below this point — warps fully independent

    // ---- chunk schedule: round 1 = warp gw; round 2 = exact spread of the
    // remaining (nck - nwarp) chunks across all warps (injective, uniform).
    const int nck   = (Brows + ROWS_W - 1) / ROWS_W;       // 4096
    const int nwarp = gridDim.x * (CTA_T >> 5);            // 2368
    const int gw    = blockIdx.x * (CTA_T >> 5) + wid;

    int mych[3];
    int nmy = 0;
    if (gw < nck) mych[nmy++] = gw;
    {
        int rem = nck - nwarp;
        if (rem > 0) {
            if (rem <= nwarp) {
                int i = (int)(((long long)gw * rem + nwarp - 1) / nwarp);
                if (i < rem && (int)(((long long)i * nwarp) / rem) == gw)
                    mych[nmy++] = nwarp + i;
            } else {
                for (int c = gw + nwarp; c < nck && nmy < 3; c += nwarp)
                    mych[nmy++] = c;
            }
        }
    }

    for (int ci = 0; ci < nmy; ci++) {
        const int mbase = mych[ci] * ROWS_W;

        const int rowb = mbase + (lid >> 2);
        const float* xb = x + (size_t)rowb * KW + (lid & 3) * 4;
        const bool pg0 = rowb < Brows;
        const bool pg1 = (rowb + 8) < Brows;

        float c[13][4];
        #pragma unroll
        for (int t = 0; t < 13; t++)
            #pragma unroll
            for (int q = 0; q < 4; q++) c[t][q] = 0.f;

        float4 pf[2];               // A raw fp32, single buffer (1-step dist)
        uint32_t bfA[26], bfB[26];  // B fragments, double-buffered

        #define LOAD_A(s) do {                                                \
            const float4 z4 = make_float4(0.f, 0.f, 0.f, 0.f);                \
            pf[0] = pg0 ? *reinterpret_cast<const float4*>(xb + (s) * 16)          : z4; \
            pf[1] = pg1 ? *reinterpret_cast<const float4*>(xb + 8 * KW + (s) * 16) : z4; \
        } while (0)

        #define LDSM_STEP(BF, s) do {                                         \
            const uint32_t sb_ = bbase + (uint32_t)(s) * BSTRIDE;             \
            ldsm_x4((BF)[0],  (BF)[1],  (BF)[2],  (BF)[3],  sb_ + boff[0]);   \
            ldsm_x4((BF)[4],  (BF)[5],  (BF)[6],  (BF)[7],  sb_ + boff[1]);   \
            ldsm_x4((BF)[8],  (BF)[9],  (BF)[10], (BF)[11], sb_ + boff[2]);   \
            ldsm_x4((BF)[12], (BF)[13], (BF)[14], (BF)[15], sb_ + boff[3]);   \
            ldsm_x4((BF)[16], (BF)[17], (BF)[18], (BF)[19], sb_ + boff[4]);   \
            ldsm_x4((BF)[20], (BF)[21], (BF)[22], (BF)[23], sb_ + boff[5]);   \
            ldsm_x2((BF)[24], (BF)[25], sb_ + bxoff);                         \
        } while (0)

        #define REBUILD_A() do {                                              \
            __half2 h01a = __floats2half2_rn(pf[0].x, pf[0].y);               \
            __half2 h23a = __floats2half2_rn(pf[0].z, pf[0].w);               \
            __half2 h01b = __floats2half2_rn(pf[1].x, pf[1].y);               \
            __half2 h23b = __floats2half2_rn(pf[1].z, pf[1].w);               \
            uint32_t u01a = *reinterpret_cast<uint32_t*>(&h01a);              \
            uint32_t u23a = *reinterpret_cast<uint32_t*>(&h23a);              \
            uint32_t u01b = *reinterpret_cast<uint32_t*>(&h01b);              \
            uint32_t u23b = *reinterpret_cast<uint32_t*>(&h23b);              \
            uint32_t s01 = __shfl_sync(0xffffffffu, u01a, src0);              \
            uint32_t s23 = __shfl_sync(0xffffffffu, u23a, src0);              \
            a0 = hi_half ? s23 : s01;                                         \
            uint32_t t01 = __shfl_sync(0xffffffffu, u01a, src1);              \
            uint32_t t23 = __shfl_sync(0xffffffffu, u23a, src1);              \
            a2 = hi_half ? t23 : t01;                                         \
            s01 = __shfl_sync(0xffffffffu, u01b, src0);                       \
            s23 = __shfl_sync(0xffffffffu, u23b, src0);                       \
            a1 = hi_half ? s23 : s01;                                         \
            t01 = __shfl_sync(0xffffffffu, u01b, src1);                       \
            t23 = __shfl_sync(0xffffffffu, u23b, src1);                       \
            a3 = hi_half ? t23 : t01;                                         \
        } while (0)

        #define STEP_PIPE(s, CUR, NXT) do {                                   \
            uint32_t a0, a1, a2, a3;                                          \
            REBUILD_A();                                                      \
            LOAD_A((s) + 1);                                                  \
            const uint32_t sbn = bbase + (uint32_t)((s) + 1) * BSTRIDE;       \
            ldsm_x4((NXT)[0], (NXT)[1], (NXT)[2], (NXT)[3], sbn + boff[0]);   \
            mma_f16(c[0],  a0, a1, a2, a3, (CUR)[0],  (CUR)[1]);              \
            mma_f16(c[1],  a0, a1, a2, a3, (CUR)[2],  (CUR)[3]);              \
            ldsm_x4((NXT)[4], (NXT)[5], (NXT)[6], (NXT)[7], sbn + boff[1]);   \
            mma_f16(c[2],  a0, a1, a2, a3, (CUR)[4],  (CUR)[5]);              \
            mma_f16(c[3],  a0, a1, a2, a3, (CUR)[6],  (CUR)[7]);              \
            ldsm_x4((NXT)[8], (NXT)[9], (NXT)[10], (NXT)[11], sbn + boff[2]); \
            mma_f16(c[4],  a0, a1, a2, a3, (CUR)[8],  (CUR)[9]);              \
            mma_f16(c[5],  a0, a1, a2, a3, (CUR)[10], (CUR)[11]);             \
            ldsm_x4((NXT)[12], (NXT)[13], (NXT)[14], (NXT)[15], sbn + boff[3]); \
            mma_f16(c[6],  a0, a1, a2, a3, (CUR)[12], (CUR)[13]);             \
            mma_f16(c[7],  a0, a1, a2, a3, (CUR)[14], (CUR)[15]);             \
            ldsm_x4((NXT)[16], (NXT)[17], (NXT)[18], (NXT)[19], sbn + boff[4]); \
            mma_f16(c[8],  a0, a1, a2, a3, (CUR)[16], (CUR)[17]);             \
            mma_f16(c[9],  a0, a1, a2, a3, (CUR)[18], (CUR)[19]);             \
            ldsm_x4((NXT)[20], (NXT)[21], (NXT)[22], (NXT)[23], sbn + boff[5]); \
            mma_f16(c[10], a0, a1, a2, a3, (CUR)[20], (CUR)[21]);             \
            mma_f16(c[11], a0, a1, a2, a3, (CUR)[22], (CUR)[23]);             \
            ldsm_x2((NXT)[24], (NXT)[25], sbn + bxoff);                       \
            mma_f16(c[12], a0, a1, a2, a3, (CUR)[24], (CUR)[25]);             \
        } while (0)

        #define STEP_LAST(CUR) do {                                           \
            uint32_t a0, a1, a2, a3;                                          \
            REBUILD_A();                                                      \
            mma_f16(c[0],  a0, a1, a2, a3, (CUR)[0],  (CUR)[1]);              \
            mma_f16(c[1],  a0, a1, a2, a3, (CUR)[2],  (CUR)[3]);              \
            mma_f16(c[2],  a0, a1, a2, a3, (CUR)[4],  (CUR)[5]);              \
            mma_f16(c[3],  a0, a1, a2, a3, (CUR)[6],  (CUR)[7]);              \
            mma_f16(c[4],  a0, a1, a2, a3, (CUR)[8],  (CUR)[9]);              \
            mma_f16(c[5],  a0, a1, a2, a3, (CUR)[10], (CUR)[11]);             \
            mma_f16(c[6],  a0, a1, a2, a3, (CUR)[12], (CUR)[13]);             \
            mma_f16(c[7],  a0, a1, a2, a3, (CUR)[14], (CUR)[15]);             \
            mma_f16(c[8],  a0, a1, a2, a3, (CUR)[16], (CUR)[17]);             \
            mma_f16(c[9],  a0, a1, a2, a3, (CUR)[18], (CUR)[19]);             \
            mma_f16(c[10], a0, a1, a2, a3, (CUR)[20], (CUR)[21]);             \
            mma_f16(c[11], a0, a1, a2, a3, (CUR)[22], (CUR)[23]);             \
            mma_f16(c[12], a0, a1, a2, a3, (CUR)[24], (CUR)[25]);             \
        } while (0)

        // prologue: A(0) + B frags(0)
        LOAD_A(0);
        LDSM_STEP(bfA, 0);

        // 48 pipelined steps (24 double-iterations), then final step 48
        #pragma unroll 1
        for (int s = 0; s < 48; s += 2) {
            STEP_PIPE(s, bfA, bfB);
            STEP_PIPE(s + 1, bfB, bfA);
        }
        STEP_LAST(bfA);   // step 48 (frags loaded during step 47)

        #undef LOAD_A
        #undef LDSM_STEP
        #undef REBUILD_A
        #undef STEP_PIPE
        #undef STEP_LAST

        // ---- epilogue: h = relu(c + b1); p = h·fc2ᵀ; quad-reduce; + b2
        float p0[10], p1[10];
        #pragma unroll
        for (int j = 0; j < 10; j++) { p0[j] = 0.f; p1[j] = 0.f; }

        #pragma unroll
        for (int t = 0; t < 13; t++) {
            #pragma unroll
            for (int e = 0; e < 2; e++) {
                int n = t * 8 + qid * 2 + e;
                if (n < 100) {
                    float h0 = fmaxf(c[t][0 + e] + b1s[n], 0.f);  // row qrow
                    float h1 = fmaxf(c[t][2 + e] + b1s[n], 0.f);  // row qrow+8
                    #pragma unroll
                    for (int j = 0; j < 10; j++) {
                        p0[j] = fmaf(h0, w2s[n][j], p0[j]);
                        p1[j] = fmaf(h1, w2s[n][j], p1[j]);
                    }
                }
            }
        }
        #pragma unroll
        for (int mask = 2; mask >= 1; mask >>= 1) {
            #pragma unroll
            for (int j = 0; j < 10; j++) {
                p0[j] += __shfl_xor_sync(0xffffffffu, p0[j], mask);
                p1[j] += __shfl_xor_sync(0xffffffffu, p1[j], mask);
            }
        }
        if (qid == 0) {
            int r0 = mbase + qrow;
            int r1 = r0 + 8;
            if (r0 < Brows) {
                #pragma unroll
                for (int j = 0; j < 10; j++)
                    out[(size_t)r0 * 10 + j] = p0[j] + b2v[j];
            }
            if (r1 < Brows) {
                #pragma unroll
                for (int j = 0; j < 10; j++)
                    out[(size_t)r1 * 10 + j] = p1[j] + b2v[j];
            }
        }
    }
}

// ---------------- launch ---------------------------------------------------

extern "C" void kernel_launch(void* const* d_in, const int* in_sizes, int n_in,
                              void* d_out, int out_size) {
    const float* x      = (const float*)d_in[0];
    const float* conv_w = (const float*)d_in[1];
    const float* fc1_w  = (const float*)d_in[2];
    const float* fc1_b  = (const float*)d_in[3];
    const float* fc2_w  = (const float*)d_in[4];
    const float* fc2_b  = (const float*)d_in[5];
    float* out = (float*)d_out;

    int Brows = in_sizes[0] / KW;

    build_w1<<<(104 * KW + 255) / 256, 256>>>(conv_w, fc1_w);

    cudaFuncSetAttribute(fused_gemm, cudaFuncAttributeMaxDynamicSharedMemorySize,
                         BSMEM);

    fused_gemm<<<148, CTA_T, BSMEM>>>(x, fc1_b, fc2_w, fc2_b, out, Brows);
}